// round 15
// baseline (speedup 1.0000x reference)
#include <cuda_runtime.h>
#include <cstdint>
#include <math.h>

#define EMBED 1024
#define HEADS 16
#define HD    64
#define BATCH 2
#define SEQ   2048
#define MROWS (BATCH*SEQ)   /* 4096 */

// ---------------------------------------------------------------------------
// Scratch (device globals: allocation-free per harness rules)
// ---------------------------------------------------------------------------
// Pair-permutation: within every 8-wide block of the contraction-ish dim,
// logical index i is stored at physical position (i<4 ? 2i : 2(i-4)+1).
// Q/K/Vt are stored tf32-rounded (Q additionally pre-scaled by 1/8*log2e),
// so flash stages them with raw cp.async byte copies.
__device__ float g_Q [BATCH*HEADS*SEQ*HD];   // [B,H,S,Dh], d-perm, tf32*QSC
__device__ float g_K [BATCH*HEADS*SEQ*HD];   // [B,H,S,Dh], d-perm, tf32
__device__ float g_Vt[BATCH*HEADS*HD*SEQ];   // [B,H,Dh,S], s-perm, tf32
__device__ float g_A [MROWS*EMBED];          // attn out, tf32, k-perm
__device__ float g_Xt[MROWS*EMBED];          // X tf32, k-perm
__device__ float g_Wt[4*EMBED*EMBED];        // W^T [n][k] tf32, k-perm

// ---------------------------------------------------------------------------
// Helpers
// ---------------------------------------------------------------------------
__device__ __forceinline__ unsigned f2tf(float f) {
    unsigned u; asm("cvt.rna.tf32.f32 %0, %1;" : "=r"(u) : "f"(f)); return u;
}
__device__ __forceinline__ uint4 tf4(float4 v) {
    uint4 u; u.x = f2tf(v.x); u.y = f2tf(v.y); u.z = f2tf(v.z); u.w = f2tf(v.w);
    return u;
}
__device__ __forceinline__ float ex2(float x) {
    float y; asm("ex2.approx.f32 %0, %1;" : "=f"(y) : "f"(x)); return y;
}
__device__ __forceinline__ int pp8(int i) {   // pair-perm within 8-block
    return (i < 4) ? 2 * i : 2 * (i - 4) + 1;
}
// D(16x8,f32) += A(16x8,tf32,row) * B(8x8,tf32,col)
__device__ __forceinline__ void mma8(float* c, const unsigned* a, const unsigned* b) {
    asm volatile(
        "mma.sync.aligned.m16n8k8.row.col.f32.tf32.tf32.f32 "
        "{%0,%1,%2,%3},{%4,%5,%6,%7},{%8,%9},{%0,%1,%2,%3};\n"
        : "+f"(c[0]), "+f"(c[1]), "+f"(c[2]), "+f"(c[3])
        : "r"(a[0]), "r"(a[1]), "r"(a[2]), "r"(a[3]), "r"(b[0]), "r"(b[1]));
}

#define CP16(dst, src) \
    asm volatile("cp.async.cg.shared.global [%0], [%1], 16;" :: "r"(dst), "l"(src))
#define CP_COMMIT() asm volatile("cp.async.commit_group;" ::: "memory")
#define CP_WAIT0()  asm volatile("cp.async.wait_group 0;" ::: "memory")

__device__ __forceinline__ uint32_t smem_u32(const void* p) {
    uint32_t a;
    asm("{ .reg .u64 t; cvta.to.shared.u64 t, %1; cvt.u32.u64 %0, t; }" : "=r"(a) : "l"(p));
    return a;
}

#define QSCALE (0.125f * 1.44269504088896340736f)

// ---------------------------------------------------------------------------
// Prep: X -> tf32, k pair-permuted (same row layout).
// ---------------------------------------------------------------------------
__global__ void __launch_bounds__(256)
prep_x(const float* __restrict__ X, float* __restrict__ Xt)
{
    size_t i = (size_t)blockIdx.x * 256 + threadIdx.x;    // float4 index
    float4 v = reinterpret_cast<const float4*>(X)[i];
    uint4  u = tf4(v);
    size_t e = i * 4;
    size_t row = e >> 10;
    int k = (int)(e & 1023);
    float* d = Xt + (row << 10) + (k & ~7) + ((k & 4) ? 1 : 0);
    d[0] = __uint_as_float(u.x);
    d[2] = __uint_as_float(u.y);
    d[4] = __uint_as_float(u.z);
    d[6] = __uint_as_float(u.w);
}

// Prep: W [k][n] -> Wt [n][k], tf32, k pair-permuted. 4 matrices via z.
__global__ void __launch_bounds__(256)
prep_w(const float* __restrict__ W0, const float* __restrict__ W1,
       const float* __restrict__ W2, const float* __restrict__ W3,
       float* __restrict__ Wt)
{
    __shared__ float s[32][33];
    const float* W = (blockIdx.z == 0) ? W0 : (blockIdx.z == 1) ? W1
                    : (blockIdx.z == 2) ? W2 : W3;
    float* o = Wt + (size_t)blockIdx.z * EMBED * EMBED;
    const int kx = blockIdx.y * 32, nx = blockIdx.x * 32;
    const int t = threadIdx.x, r = t >> 3, c = t & 7;

    float4 v = *reinterpret_cast<const float4*>(&W[(size_t)(kx + r) * EMBED + nx + c * 4]);
    int rp = (r & 24) | pp8(r & 7);
    s[c * 4 + 0][rp] = __uint_as_float(f2tf(v.x));
    s[c * 4 + 1][rp] = __uint_as_float(f2tf(v.y));
    s[c * 4 + 2][rp] = __uint_as_float(f2tf(v.z));
    s[c * 4 + 3][rp] = __uint_as_float(f2tf(v.w));
    __syncthreads();
    float4 u;
    u.x = s[r][c * 4 + 0]; u.y = s[r][c * 4 + 1];
    u.z = s[r][c * 4 + 2]; u.w = s[r][c * 4 + 3];
    *reinterpret_cast<float4*>(&o[(size_t)(nx + r) * EMBED + kx + c * 4]) = u;
}

// ---------------------------------------------------------------------------
// Pipelined GEMM: C = A @ W^T + bias, tile 128x128x32, uint2 fragment loads,
// 2-stage cp.async, one barrier per k-tile.
// mode 0: K   -> [B,H,S,Dh] d-perm, tf32-rounded
// mode 1: Q   -> [B,H,S,Dh] d-perm, tf32(v*QSCALE)
// mode 2: Vt  -> [B,H,Dh,S] s-perm, tf32-rounded
// mode 3: out -> row-major [M,N], plain fp32
// ---------------------------------------------------------------------------
#define BM 128
#define BN 128
#define BK 32
#define ASTR 40
#define BSTR 40
#define A_BUF (BM*ASTR*4)
#define B_BUF (BN*BSTR*4)
#define NSTAGE 2
#define PIPE_SMEM (NSTAGE*(A_BUF+B_BUF))   /* 81920 B */
#define NKT (EMBED/BK)

__device__ __forceinline__ void
gemm_pipe_body(const float* __restrict__ A, const float* __restrict__ W,
               const float* __restrict__ bias, float* __restrict__ out, int mode)
{
    extern __shared__ char sm[];
    const uint32_t sb = smem_u32(sm);
    const int t    = threadIdx.x;
    const int w    = t >> 5;
    const int lane = t & 31;
    const int gid  = lane >> 2;
    const int tig  = lane & 3;
    const int wm   = w >> 2;
    const int wn   = w & 3;
    const int m0   = blockIdx.y * BM;
    const int n0   = blockIdx.x * BN;

    uint32_t aoff[NSTAGE], boff[NSTAGE];
#pragma unroll
    for (int s = 0; s < NSTAGE; s++) {
        aoff[s] = sb + s * A_BUF;
        boff[s] = sb + NSTAGE * A_BUF + s * B_BUF;
    }

    auto issue = [&](int slot, int k0) {
#pragma unroll
        for (int it = 0; it < 4; it++) {
            int idx = t + it * 256;
            int r = idx >> 3, c = idx & 7;
            CP16(aoff[slot] + r * (ASTR * 4) + c * 16,
                 A + (size_t)(m0 + r) * EMBED + k0 + c * 4);
        }
#pragma unroll
        for (int it = 0; it < 4; it++) {
            int idx = t + it * 256;
            int r = idx >> 3, c = idx & 7;
            CP16(boff[slot] + r * (BSTR * 4) + c * 16,
                 W + (size_t)(n0 + r) * EMBED + k0 + c * 4);
        }
        CP_COMMIT();
    };

    float acc[4][4][4];
#pragma unroll
    for (int i = 0; i < 4; i++)
#pragma unroll
        for (int j = 0; j < 4; j++)
#pragma unroll
            for (int r = 0; r < 4; r++) acc[i][j][r] = 0.f;

    issue(0, 0);

    for (int kt = 0; kt < NKT; kt++) {
        const int slot = kt & 1;
        CP_WAIT0();
        __syncthreads();
        if (kt + 1 < NKT) issue(slot ^ 1, (kt + 1) * BK);

        const unsigned (*As)[ASTR] = (const unsigned (*)[ASTR])(sm + slot * A_BUF);
        const unsigned (*Bs)[BSTR] =
            (const unsigned (*)[BSTR])(sm + NSTAGE * A_BUF + slot * B_BUF);

#pragma unroll
        for (int kk = 0; kk < BK; kk += 8) {
            unsigned af[4][4], bf[4][2];
#pragma unroll
            for (int i = 0; i < 4; i++) {
                int mb = wm * 64 + i * 16;
                uint2 lo = *reinterpret_cast<const uint2*>(&As[mb + gid    ][kk + 2 * tig]);
                uint2 hi = *reinterpret_cast<const uint2*>(&As[mb + gid + 8][kk + 2 * tig]);
                af[i][0] = lo.x; af[i][1] = hi.x; af[i][2] = lo.y; af[i][3] = hi.y;
            }
#pragma unroll
            for (int j = 0; j < 4; j++) {
                int nb = wn * 32 + j * 8;
                uint2 bb = *reinterpret_cast<const uint2*>(&Bs[nb + gid][kk + 2 * tig]);
                bf[j][0] = bb.x; bf[j][1] = bb.y;
            }
#pragma unroll
            for (int i = 0; i < 4; i++)
#pragma unroll
                for (int j = 0; j < 4; j++)
                    mma8(acc[i][j], af[i], bf[j]);
        }
    }

    // Epilogue (scalar stores; perms + tf32 rounding applied producer-side)
#pragma unroll
    for (int i = 0; i < 4; i++) {
#pragma unroll
        for (int j = 0; j < 4; j++) {
#pragma unroll
            for (int r = 0; r < 4; r++) {
                int m = m0 + wm * 64 + i * 16 + gid + ((r >> 1) << 3);
                int n = n0 + wn * 32 + j * 8 + 2 * tig + (r & 1);
                float v = acc[i][j][r] + bias[n];
                if (mode == 3) {
                    out[(size_t)m * EMBED + n] = v;
                } else {
                    int b = m >> 11, s = m & (SEQ - 1);
                    int h = n >> 6,  d = n & (HD - 1);
                    if (mode == 2) {
                        int sp = (s & ~7) | pp8(s & 7);
                        out[(((size_t)(b * HEADS + h)) * HD + d) * SEQ + sp] =
                            __uint_as_float(f2tf(v));
                    } else {
                        int dp = (d & 56) | pp8(d & 7);
                        float vv = (mode == 1) ? v * QSCALE : v;
                        out[(((size_t)(b * HEADS + h)) * SEQ + s) * HD + dp] =
                            __uint_as_float(f2tf(vv));
                    }
                }
            }
        }
    }
}

__global__ void __launch_bounds__(256, 2)
gemm_qkv(const float* __restrict__ Xt, const float* __restrict__ Wt,
         const float* __restrict__ bq, const float* __restrict__ bk,
         const float* __restrict__ bv,
         float* __restrict__ Qo, float* __restrict__ Ko, float* __restrict__ Vo)
{
    if (blockIdx.z == 0)
        gemm_pipe_body(Xt, Wt,                 bq, Qo, 1);
    else if (blockIdx.z == 1)
        gemm_pipe_body(Xt, Wt + EMBED*EMBED,   bk, Ko, 0);
    else
        gemm_pipe_body(Xt, Wt + 2*EMBED*EMBED, bv, Vo, 2);
}

__global__ void __launch_bounds__(256, 2)
gemm_out(const float* __restrict__ Aa, const float* __restrict__ Wt,
         const float* __restrict__ bias, float* __restrict__ out)
{
    gemm_pipe_body(Aa, Wt + 3*EMBED*EMBED, bias, out, 3);
}

// ---------------------------------------------------------------------------
// Flash attention v4: Q/K/Vt arrive tf32-rounded (Q pre-scaled), pair-permuted.
// All staging is raw cp.async (no LDG->reg->cvt->STS, no f2tf in staging).
// Double-buffered K/V, ONE barrier + ONE wait_group per kv block.
// ---------------------------------------------------------------------------
#define BQ  64
#define BKV 64
#define FL_STRIDE 72
#define TILE_WORDS (BKV * FL_STRIDE)              /* 4608 */
#define FLASH_SMEM_BYTES (4 * TILE_WORDS * 4)     /* 73728 */

__global__ void __launch_bounds__(128, 3)
flash_attn(const float* __restrict__ Q, const float* __restrict__ K,
           const float* __restrict__ Vt, float* __restrict__ outA)
{
    extern __shared__ unsigned sh[];
    unsigned (*Ks0)[FL_STRIDE] = (unsigned (*)[FL_STRIDE])(sh);
    unsigned (*Vs0)[FL_STRIDE] = (unsigned (*)[FL_STRIDE])(sh + TILE_WORDS);
    unsigned (*Ks1)[FL_STRIDE] = (unsigned (*)[FL_STRIDE])(sh + 2 * TILE_WORDS);
    unsigned (*Vs1)[FL_STRIDE] = (unsigned (*)[FL_STRIDE])(sh + 3 * TILE_WORDS);
    const uint32_t sbase = smem_u32(sh);

    const int tid  = threadIdx.x;
    const int w    = tid >> 5;
    const int lane = tid & 31;
    const int gid  = lane >> 2;
    const int tig  = lane & 3;
    const int bh   = blockIdx.y;
    const int q0   = blockIdx.x * BQ;
    const int mq   = w * 16;

    const float* Qp = Q  + (size_t)bh * SEQ * HD;
    const float* Kp = K  + (size_t)bh * SEQ * HD;
    const float* Vp = Vt + (size_t)bh * HD * SEQ;

    const int ldr = tid >> 4;                       // 0..7
    const int ldc = (tid & 15) * 4;                 // word 0..60
    const uint32_t so = (uint32_t)(ldr * FL_STRIDE + ldc) * 4;  // per-thread smem byte offset
    const uint32_t rowstep = 8u * FL_STRIDE * 4u;   // 8 rows per staging iter

    // ---- Q stage via cp.async into Ks0 (64 rows; already scaled+tf32) ----
#pragma unroll
    for (int it = 0; it < 8; it++)
        CP16(sbase + so + it * rowstep,
             Qp + (size_t)(q0 + ldr + it * 8) * HD + ldc);
    CP_COMMIT(); CP_WAIT0();
    __syncthreads();
    unsigned qa[8][4];
#pragma unroll
    for (int kk = 0; kk < 8; kk++) {
        uint2 lo = *reinterpret_cast<const uint2*>(&Ks0[mq + gid    ][kk * 8 + 2 * tig]);
        uint2 hi = *reinterpret_cast<const uint2*>(&Ks0[mq + gid + 8][kk * 8 + 2 * tig]);
        qa[kk][0] = lo.x; qa[kk][1] = hi.x; qa[kk][2] = lo.y; qa[kk][3] = hi.y;
    }
    __syncthreads();

    // ---- prologue: tile 0 into buffer 0 ----
    const uint32_t KB0 = sbase, VB0 = sbase + TILE_WORDS * 4;
    const uint32_t KB1 = sbase + 2 * TILE_WORDS * 4, VB1 = sbase + 3 * TILE_WORDS * 4;
#pragma unroll
    for (int it = 0; it < 8; it++) {
        int r = ldr + it * 8;
        CP16(KB0 + so + it * rowstep, Kp + (size_t)r * HD + ldc);
        CP16(VB0 + so + it * rowstep, Vp + (size_t)r * SEQ + ldc);
    }
    CP_COMMIT();

    float o[8][4];
#pragma unroll
    for (int j = 0; j < 8; j++)
#pragma unroll
        for (int r = 0; r < 4; r++) o[j][r] = 0.f;
    float mrow[2] = {-1e30f, -1e30f};
    float lrow[2] = {0.f, 0.f};

    const int l0 = (lane & 28) | (tig >> 1);
    const bool odd = (tig & 1);

    for (int kb = 0; kb < SEQ / BKV; kb++) {
        const unsigned (*Kc)[FL_STRIDE] = (kb & 1) ? Ks1 : Ks0;
        const unsigned (*Vc)[FL_STRIDE] = (kb & 1) ? Vs1 : Vs0;
        const uint32_t KnB = (kb & 1) ? KB0 : KB1;
        const uint32_t VnB = (kb & 1) ? VB0 : VB1;
        const bool has_next = (kb + 1) < (SEQ / BKV);
        const int sN = (kb + 1) * BKV;

        CP_WAIT0();                 // current tile resident
        __syncthreads();            // also: all warps done reading the buffer
                                    // the upcoming issue will overwrite
        if (has_next) {
#pragma unroll
            for (int it = 0; it < 8; it++) {
                int r = ldr + it * 8;
                CP16(KnB + so + it * rowstep, Kp + (size_t)(sN + r) * HD + ldc);
                CP16(VnB + so + it * rowstep, Vp + (size_t)r * SEQ + sN + ldc);
            }
            CP_COMMIT();
        }

        // S = Q @ K^T
        float s[8][4];
#pragma unroll
        for (int j = 0; j < 8; j++)
#pragma unroll
            for (int r = 0; r < 4; r++) s[j][r] = 0.f;
#pragma unroll
        for (int kk = 0; kk < 8; kk++) {
#pragma unroll
            for (int j = 0; j < 8; j++) {
                uint2 bb = *reinterpret_cast<const uint2*>(&Kc[j * 8 + gid][kk * 8 + 2 * tig]);
                unsigned b[2] = { bb.x, bb.y };
                mma8(s[j], qa[kk], b);
            }
        }

        // Online softmax (base 2)
#pragma unroll
        for (int rr = 0; rr < 2; rr++) {
            float mx = -1e30f;
#pragma unroll
            for (int j = 0; j < 8; j++) {
                mx = fmaxf(mx, s[j][rr * 2]);
                mx = fmaxf(mx, s[j][rr * 2 + 1]);
            }
            mx = fmaxf(mx, __shfl_xor_sync(0xffffffffu, mx, 1));
            mx = fmaxf(mx, __shfl_xor_sync(0xffffffffu, mx, 2));
            float mnew = fmaxf(mrow[rr], mx);
            float corr = ex2(mrow[rr] - mnew);
            float rs = 0.f;
#pragma unroll
            for (int j = 0; j < 8; j++) {
                float e0 = ex2(s[j][rr * 2]     - mnew);
                float e1 = ex2(s[j][rr * 2 + 1] - mnew);
                s[j][rr * 2] = e0; s[j][rr * 2 + 1] = e1;
                rs += e0 + e1;
            }
            rs += __shfl_xor_sync(0xffffffffu, rs, 1);
            rs += __shfl_xor_sync(0xffffffffu, rs, 2);
            lrow[rr] = lrow[rr] * corr + rs;
            mrow[rr] = mnew;
#pragma unroll
            for (int j = 0; j < 8; j++) {
                o[j][rr * 2]     *= corr;
                o[j][rr * 2 + 1] *= corr;
            }
        }

        // O += P @ V (P transposed via shuffles; V b-frags via LDS.64)
#pragma unroll
        for (int j = 0; j < 8; j++) {
            unsigned v0 = f2tf(s[j][0]), v1 = f2tf(s[j][1]);
            unsigned v2 = f2tf(s[j][2]), v3 = f2tf(s[j][3]);
            unsigned t00 = __shfl_sync(0xffffffffu, v0, l0);
            unsigned t01 = __shfl_sync(0xffffffffu, v1, l0);
            unsigned t02 = __shfl_sync(0xffffffffu, v2, l0);
            unsigned t03 = __shfl_sync(0xffffffffu, v3, l0);
            unsigned t10 = __shfl_sync(0xffffffffu, v0, l0 + 2);
            unsigned t11 = __shfl_sync(0xffffffffu, v1, l0 + 2);
            unsigned t12 = __shfl_sync(0xffffffffu, v2, l0 + 2);
            unsigned t13 = __shfl_sync(0xffffffffu, v3, l0 + 2);
            unsigned a[4];
            a[0] = odd ? t01 : t00;
            a[1] = odd ? t03 : t02;
            a[2] = odd ? t11 : t10;
            a[3] = odd ? t13 : t12;
#pragma unroll
            for (int jj = 0; jj < 8; jj++) {
                uint2 bb = *reinterpret_cast<const uint2*>(&Vc[jj * 8 + gid][j * 8 + 2 * tig]);
                unsigned b[2] = { bb.x, bb.y };
                mma8(o[jj], a, b);
            }
        }
        // no trailing barrier: next iteration's top barrier orders buffer reuse
    }

    // Epilogue: write g_A tf32-rounded with the gemm k pair-perm
    const int b = bh >> 4, h = bh & 15;
    const float inv0 = 1.f / lrow[0];
    const float inv1 = 1.f / lrow[1];
    const int row0 = q0 + mq + gid;
    const int row1 = row0 + 8;
    const int cofs = (tig < 2) ? 4 * tig : 4 * tig - 7;
#pragma unroll
    for (int jj = 0; jj < 8; jj++) {
        int c0 = h * HD + jj * 8 + cofs;
        outA[(size_t)(b * SEQ + row0) * EMBED + c0    ] =
            __uint_as_float(f2tf(o[jj][0] * inv0));
        outA[(size_t)(b * SEQ + row0) * EMBED + c0 + 2] =
            __uint_as_float(f2tf(o[jj][1] * inv0));
        outA[(size_t)(b * SEQ + row1) * EMBED + c0    ] =
            __uint_as_float(f2tf(o[jj][2] * inv1));
        outA[(size_t)(b * SEQ + row1) * EMBED + c0 + 2] =
            __uint_as_float(f2tf(o[jj][3] * inv1));
    }
}

// ---------------------------------------------------------------------------
// Launch
// ---------------------------------------------------------------------------
extern "C" void kernel_launch(void* const* d_in, const int* in_sizes, int n_in,
                              void* d_out, int out_size)
{
    const float* X  = (const float*)d_in[0];
    const float* Wq = (const float*)d_in[1];
    const float* bq = (const float*)d_in[2];
    const float* Wk = (const float*)d_in[3];
    const float* bk = (const float*)d_in[4];
    const float* Wv = (const float*)d_in[5];
    const float* bv = (const float*)d_in[6];
    const float* Wo = (const float*)d_in[7];
    const float* bo = (const float*)d_in[8];
    float* out = (float*)d_out;

    float *qb, *kb, *vtb, *ab, *xtb, *wtb;
    cudaGetSymbolAddress((void**)&qb,  g_Q);
    cudaGetSymbolAddress((void**)&kb,  g_K);
    cudaGetSymbolAddress((void**)&vtb, g_Vt);
    cudaGetSymbolAddress((void**)&ab,  g_A);
    cudaGetSymbolAddress((void**)&xtb, g_Xt);
    cudaGetSymbolAddress((void**)&wtb, g_Wt);

    cudaFuncSetAttribute(flash_attn, cudaFuncAttributeMaxDynamicSharedMemorySize,
                         FLASH_SMEM_BYTES);
    cudaFuncSetAttribute(gemm_qkv, cudaFuncAttributeMaxDynamicSharedMemorySize,
                         PIPE_SMEM);
    cudaFuncSetAttribute(gemm_out, cudaFuncAttributeMaxDynamicSharedMemorySize,
                         PIPE_SMEM);

    // 1) prep: X tf32 + k-perm; W transpose + tf32 + k-perm
    prep_x<<<(MROWS * EMBED / 4) / 256, 256>>>(X, xtb);
    dim3 wgrid(EMBED / 32, EMBED / 32, 4);
    prep_w<<<wgrid, 256>>>(Wq, Wk, Wv, Wo, wtb);

    // 2) fused QKV projections (Q pre-scaled + tf32; K/Vt tf32)
    dim3 qkvgrid(EMBED / BN, MROWS / BM, 3);     // (8, 32, 3)
    gemm_qkv<<<qkvgrid, 256, PIPE_SMEM>>>(xtb, wtb, bq, bk, bv, qb, kb, vtb);

    // 3) attention
    dim3 fgrid(SEQ / BQ, BATCH * HEADS);         // (32, 32)
    flash_attn<<<fgrid, 128, FLASH_SMEM_BYTES>>>(qb, kb, vtb, ab);

    // 4) output projection
    dim3 ogrid(EMBED / BN, MROWS / BM);          // (8, 32)
    gemm_out<<<ogrid, 256, PIPE_SMEM>>>(ab, wtb, bo, out);
}

// round 16
// speedup vs baseline: 1.4414x; 1.4414x over previous
#include <cuda_runtime.h>
#include <cstdint>
#include <math.h>

#define EMBED 1024
#define HEADS 16
#define HD    64
#define BATCH 2
#define SEQ   2048
#define MROWS (BATCH*SEQ)   /* 4096 */

// ---------------------------------------------------------------------------
// Scratch (device globals: allocation-free per harness rules)
// ---------------------------------------------------------------------------
// Pair-permutation: within every 8-wide block of the contraction-ish dim,
// logical index i is stored at physical position (i<4 ? 2i : 2(i-4)+1).
// Q/K/Vt are stored tf32-rounded (Q additionally pre-scaled by 1/8*log2e),
// so flash staging is a raw bit-copy (no CVT anywhere in the mainloop).
__device__ float g_Q [BATCH*HEADS*SEQ*HD];   // [B,H,S,Dh], d-perm, tf32*QSC
__device__ float g_K [BATCH*HEADS*SEQ*HD];   // [B,H,S,Dh], d-perm, tf32
__device__ float g_Vt[BATCH*HEADS*HD*SEQ];   // [B,H,Dh,S], s-perm, tf32
__device__ float g_A [MROWS*EMBED];          // attn out, tf32, k-perm
__device__ float g_Xt[MROWS*EMBED];          // X tf32, k-perm
__device__ float g_Wt[4*EMBED*EMBED];        // W^T [n][k] tf32, k-perm

// ---------------------------------------------------------------------------
// Helpers
// ---------------------------------------------------------------------------
__device__ __forceinline__ unsigned f2tf(float f) {
    unsigned u; asm("cvt.rna.tf32.f32 %0, %1;" : "=r"(u) : "f"(f)); return u;
}
__device__ __forceinline__ uint4 tf4(float4 v) {
    uint4 u; u.x = f2tf(v.x); u.y = f2tf(v.y); u.z = f2tf(v.z); u.w = f2tf(v.w);
    return u;
}
__device__ __forceinline__ float ex2(float x) {
    float y; asm("ex2.approx.f32 %0, %1;" : "=f"(y) : "f"(x)); return y;
}
__device__ __forceinline__ int pp8(int i) {   // pair-perm within 8-block
    return (i < 4) ? 2 * i : 2 * (i - 4) + 1;
}
// D(16x8,f32) += A(16x8,tf32,row) * B(8x8,tf32,col)
__device__ __forceinline__ void mma8(float* c, const unsigned* a, const unsigned* b) {
    asm volatile(
        "mma.sync.aligned.m16n8k8.row.col.f32.tf32.tf32.f32 "
        "{%0,%1,%2,%3},{%4,%5,%6,%7},{%8,%9},{%0,%1,%2,%3};\n"
        : "+f"(c[0]), "+f"(c[1]), "+f"(c[2]), "+f"(c[3])
        : "r"(a[0]), "r"(a[1]), "r"(a[2]), "r"(a[3]), "r"(b[0]), "r"(b[1]));
}

#define CP16(dst, src) \
    asm volatile("cp.async.cg.shared.global [%0], [%1], 16;" :: "r"(dst), "l"(src))
#define CP_COMMIT() asm volatile("cp.async.commit_group;" ::: "memory")
#define CP_WAIT0()  asm volatile("cp.async.wait_group 0;" ::: "memory")

__device__ __forceinline__ uint32_t smem_u32(const void* p) {
    uint32_t a;
    asm("{ .reg .u64 t; cvta.to.shared.u64 t, %1; cvt.u32.u64 %0, t; }" : "=r"(a) : "l"(p));
    return a;
}

#define QSCALE (0.125f * 1.44269504088896340736f)

// ---------------------------------------------------------------------------
// Prep: X -> tf32, k pair-permuted (same row layout).
// ---------------------------------------------------------------------------
__global__ void __launch_bounds__(256)
prep_x(const float* __restrict__ X, float* __restrict__ Xt)
{
    size_t i = (size_t)blockIdx.x * 256 + threadIdx.x;    // float4 index
    float4 v = reinterpret_cast<const float4*>(X)[i];
    uint4  u = tf4(v);
    size_t e = i * 4;
    size_t row = e >> 10;
    int k = (int)(e & 1023);
    float* d = Xt + (row << 10) + (k & ~7) + ((k & 4) ? 1 : 0);
    d[0] = __uint_as_float(u.x);
    d[2] = __uint_as_float(u.y);
    d[4] = __uint_as_float(u.z);
    d[6] = __uint_as_float(u.w);
}

// Prep: W [k][n] -> Wt [n][k], tf32, k pair-permuted. 4 matrices via z.
__global__ void __launch_bounds__(256)
prep_w(const float* __restrict__ W0, const float* __restrict__ W1,
       const float* __restrict__ W2, const float* __restrict__ W3,
       float* __restrict__ Wt)
{
    __shared__ float s[32][33];
    const float* W = (blockIdx.z == 0) ? W0 : (blockIdx.z == 1) ? W1
                    : (blockIdx.z == 2) ? W2 : W3;
    float* o = Wt + (size_t)blockIdx.z * EMBED * EMBED;
    const int kx = blockIdx.y * 32, nx = blockIdx.x * 32;
    const int t = threadIdx.x, r = t >> 3, c = t & 7;

    float4 v = *reinterpret_cast<const float4*>(&W[(size_t)(kx + r) * EMBED + nx + c * 4]);
    int rp = (r & 24) | pp8(r & 7);
    s[c * 4 + 0][rp] = __uint_as_float(f2tf(v.x));
    s[c * 4 + 1][rp] = __uint_as_float(f2tf(v.y));
    s[c * 4 + 2][rp] = __uint_as_float(f2tf(v.z));
    s[c * 4 + 3][rp] = __uint_as_float(f2tf(v.w));
    __syncthreads();
    float4 u;
    u.x = s[r][c * 4 + 0]; u.y = s[r][c * 4 + 1];
    u.z = s[r][c * 4 + 2]; u.w = s[r][c * 4 + 3];
    *reinterpret_cast<float4*>(&o[(size_t)(nx + r) * EMBED + kx + c * 4]) = u;
}

// ---------------------------------------------------------------------------
// Pipelined GEMM: C = A @ W^T + bias, tile 128x128x32, uint2 fragment loads,
// 2-stage cp.async, one barrier per k-tile.
// mode 0: K   -> [B,H,S,Dh] d-perm, tf32-rounded
// mode 1: Q   -> [B,H,S,Dh] d-perm, tf32(v*QSCALE)
// mode 2: Vt  -> [B,H,Dh,S] s-perm, tf32-rounded
// mode 3: out -> row-major [M,N], plain fp32
// ---------------------------------------------------------------------------
#define BM 128
#define BN 128
#define BK 32
#define ASTR 40
#define BSTR 40
#define A_BUF (BM*ASTR*4)
#define B_BUF (BN*BSTR*4)
#define NSTAGE 2
#define PIPE_SMEM (NSTAGE*(A_BUF+B_BUF))   /* 81920 B */
#define NKT (EMBED/BK)

__device__ __forceinline__ void
gemm_pipe_body(const float* __restrict__ A, const float* __restrict__ W,
               const float* __restrict__ bias, float* __restrict__ out, int mode)
{
    extern __shared__ char sm[];
    const uint32_t sb = smem_u32(sm);
    const int t    = threadIdx.x;
    const int w    = t >> 5;
    const int lane = t & 31;
    const int gid  = lane >> 2;
    const int tig  = lane & 3;
    const int wm   = w >> 2;
    const int wn   = w & 3;
    const int m0   = blockIdx.y * BM;
    const int n0   = blockIdx.x * BN;

    uint32_t aoff[NSTAGE], boff[NSTAGE];
#pragma unroll
    for (int s = 0; s < NSTAGE; s++) {
        aoff[s] = sb + s * A_BUF;
        boff[s] = sb + NSTAGE * A_BUF + s * B_BUF;
    }

    auto issue = [&](int slot, int k0) {
#pragma unroll
        for (int it = 0; it < 4; it++) {
            int idx = t + it * 256;
            int r = idx >> 3, c = idx & 7;
            CP16(aoff[slot] + r * (ASTR * 4) + c * 16,
                 A + (size_t)(m0 + r) * EMBED + k0 + c * 4);
        }
#pragma unroll
        for (int it = 0; it < 4; it++) {
            int idx = t + it * 256;
            int r = idx >> 3, c = idx & 7;
            CP16(boff[slot] + r * (BSTR * 4) + c * 16,
                 W + (size_t)(n0 + r) * EMBED + k0 + c * 4);
        }
        CP_COMMIT();
    };

    float acc[4][4][4];
#pragma unroll
    for (int i = 0; i < 4; i++)
#pragma unroll
        for (int j = 0; j < 4; j++)
#pragma unroll
            for (int r = 0; r < 4; r++) acc[i][j][r] = 0.f;

    issue(0, 0);

    for (int kt = 0; kt < NKT; kt++) {
        const int slot = kt & 1;
        CP_WAIT0();
        __syncthreads();
        if (kt + 1 < NKT) issue(slot ^ 1, (kt + 1) * BK);

        const unsigned (*As)[ASTR] = (const unsigned (*)[ASTR])(sm + slot * A_BUF);
        const unsigned (*Bs)[BSTR] =
            (const unsigned (*)[BSTR])(sm + NSTAGE * A_BUF + slot * B_BUF);

#pragma unroll
        for (int kk = 0; kk < BK; kk += 8) {
            unsigned af[4][4], bf[4][2];
#pragma unroll
            for (int i = 0; i < 4; i++) {
                int mb = wm * 64 + i * 16;
                uint2 lo = *reinterpret_cast<const uint2*>(&As[mb + gid    ][kk + 2 * tig]);
                uint2 hi = *reinterpret_cast<const uint2*>(&As[mb + gid + 8][kk + 2 * tig]);
                af[i][0] = lo.x; af[i][1] = hi.x; af[i][2] = lo.y; af[i][3] = hi.y;
            }
#pragma unroll
            for (int j = 0; j < 4; j++) {
                int nb = wn * 32 + j * 8;
                uint2 bb = *reinterpret_cast<const uint2*>(&Bs[nb + gid][kk + 2 * tig]);
                bf[j][0] = bb.x; bf[j][1] = bb.y;
            }
#pragma unroll
            for (int i = 0; i < 4; i++)
#pragma unroll
                for (int j = 0; j < 4; j++)
                    mma8(acc[i][j], af[i], bf[j]);
        }
    }

    // Epilogue (scalar stores; perms + tf32 rounding applied producer-side)
#pragma unroll
    for (int i = 0; i < 4; i++) {
#pragma unroll
        for (int j = 0; j < 4; j++) {
#pragma unroll
            for (int r = 0; r < 4; r++) {
                int m = m0 + wm * 64 + i * 16 + gid + ((r >> 1) << 3);
                int n = n0 + wn * 32 + j * 8 + 2 * tig + (r & 1);
                float v = acc[i][j][r] + bias[n];
                if (mode == 3) {
                    out[(size_t)m * EMBED + n] = v;
                } else {
                    int b = m >> 11, s = m & (SEQ - 1);
                    int h = n >> 6,  d = n & (HD - 1);
                    if (mode == 2) {
                        int sp = (s & ~7) | pp8(s & 7);
                        out[(((size_t)(b * HEADS + h)) * HD + d) * SEQ + sp] =
                            __uint_as_float(f2tf(v));
                    } else {
                        int dp = (d & 56) | pp8(d & 7);
                        float vv = (mode == 1) ? v * QSCALE : v;
                        out[(((size_t)(b * HEADS + h)) * SEQ + s) * HD + dp] =
                            __uint_as_float(f2tf(vv));
                    }
                }
            }
        }
    }
}

__global__ void __launch_bounds__(256, 2)
gemm_qkv(const float* __restrict__ Xt, const float* __restrict__ Wt,
         const float* __restrict__ bq, const float* __restrict__ bk,
         const float* __restrict__ bv,
         float* __restrict__ Qo, float* __restrict__ Ko, float* __restrict__ Vo)
{
    if (blockIdx.z == 0)
        gemm_pipe_body(Xt, Wt,                 bq, Qo, 1);
    else if (blockIdx.z == 1)
        gemm_pipe_body(Xt, Wt + EMBED*EMBED,   bk, Ko, 0);
    else
        gemm_pipe_body(Xt, Wt + 2*EMBED*EMBED, bv, Vo, 2);
}

__global__ void __launch_bounds__(256, 2)
gemm_out(const float* __restrict__ Aa, const float* __restrict__ Wt,
         const float* __restrict__ bias, float* __restrict__ out)
{
    gemm_pipe_body(Aa, Wt + 3*EMBED*EMBED, bias, out, 3);
}

// ---------------------------------------------------------------------------
// Flash attention v5 (hybrid): Q/K/Vt arrive tf32-rounded + permuted, so
// staging is a pure bit-copy. Uses the register-prefetch staging that
// measured best (R12) but with ZERO conversions in the loop:
//   prefetch next K (LDG.128) behind S-matmul; commit K + prefetch V behind
//   softmax; commit V after PV. One __syncthreads per kv block.
// ---------------------------------------------------------------------------
#define BQ  64
#define BKV 64
#define FL_STRIDE 72
#define TILE_WORDS (BKV * FL_STRIDE)              /* 4608 */
#define FLASH_SMEM_BYTES (4 * TILE_WORDS * 4)     /* 73728 */

__global__ void __launch_bounds__(128, 3)
flash_attn(const float* __restrict__ Q, const float* __restrict__ K,
           const float* __restrict__ Vt, float* __restrict__ outA)
{
    extern __shared__ unsigned sh[];
    unsigned (*Ks0)[FL_STRIDE] = (unsigned (*)[FL_STRIDE])(sh);
    unsigned (*Vs0)[FL_STRIDE] = (unsigned (*)[FL_STRIDE])(sh + TILE_WORDS);
    unsigned (*Ks1)[FL_STRIDE] = (unsigned (*)[FL_STRIDE])(sh + 2 * TILE_WORDS);
    unsigned (*Vs1)[FL_STRIDE] = (unsigned (*)[FL_STRIDE])(sh + 3 * TILE_WORDS);

    const int tid  = threadIdx.x;
    const int w    = tid >> 5;
    const int lane = tid & 31;
    const int gid  = lane >> 2;
    const int tig  = lane & 3;
    const int bh   = blockIdx.y;
    const int q0   = blockIdx.x * BQ;
    const int mq   = w * 16;

    const float* Qp = Q  + (size_t)bh * SEQ * HD;
    const float* Kp = K  + (size_t)bh * SEQ * HD;
    const float* Vp = Vt + (size_t)bh * HD * SEQ;

    const int ldr = tid >> 4;                       // 0..7
    const int ldc = (tid & 15) * 4;                 // word 0..60

    // ---- Q stage (pure copy; pre-scaled tf32 in gmem) ----
#pragma unroll
    for (int it = 0; it < 8; it++) {
        int r = ldr + it * 8;
        *reinterpret_cast<uint4*>(&Ks0[r][ldc]) =
            *reinterpret_cast<const uint4*>(&Qp[(size_t)(q0 + r) * HD + ldc]);
    }
    __syncthreads();
    unsigned qa[8][4];
#pragma unroll
    for (int kk = 0; kk < 8; kk++) {
        uint2 lo = *reinterpret_cast<const uint2*>(&Ks0[mq + gid    ][kk * 8 + 2 * tig]);
        uint2 hi = *reinterpret_cast<const uint2*>(&Ks0[mq + gid + 8][kk * 8 + 2 * tig]);
        qa[kk][0] = lo.x; qa[kk][1] = hi.x; qa[kk][2] = lo.y; qa[kk][3] = hi.y;
    }
    __syncthreads();

    // ---- prologue: tile 0 (pure copy) ----
#pragma unroll
    for (int it = 0; it < 8; it++) {
        int r = ldr + it * 8;
        *reinterpret_cast<uint4*>(&Ks0[r][ldc]) =
            *reinterpret_cast<const uint4*>(&Kp[(size_t)r * HD + ldc]);
        *reinterpret_cast<uint4*>(&Vs0[r][ldc]) =
            *reinterpret_cast<const uint4*>(&Vp[(size_t)r * SEQ + ldc]);
    }
    __syncthreads();

    float o[8][4];
#pragma unroll
    for (int j = 0; j < 8; j++)
#pragma unroll
        for (int r = 0; r < 4; r++) o[j][r] = 0.f;
    float mrow[2] = {-1e30f, -1e30f};
    float lrow[2] = {0.f, 0.f};

    const int l0 = (lane & 28) | (tig >> 1);
    const bool odd = (tig & 1);

    for (int kb = 0; kb < SEQ / BKV; kb++) {
        const unsigned (*Kc)[FL_STRIDE] = (kb & 1) ? Ks1 : Ks0;
        const unsigned (*Vc)[FL_STRIDE] = (kb & 1) ? Vs1 : Vs0;
        unsigned (*Kn)[FL_STRIDE] = (kb & 1) ? Ks0 : Ks1;
        unsigned (*Vn)[FL_STRIDE] = (kb & 1) ? Vs0 : Vs1;
        const bool has_next = (kb + 1) < (SEQ / BKV);
        const int sN = (kb + 1) * BKV;

        uint4 ld[8];
        if (has_next) {                    // prefetch next K behind S-matmul
#pragma unroll
            for (int it = 0; it < 8; it++) {
                int r = ldr + it * 8;
                ld[it] = *reinterpret_cast<const uint4*>(&Kp[(size_t)(sN + r) * HD + ldc]);
            }
        }

        // S = Q @ K^T  (b-frags via LDS.64)
        float s[8][4];
#pragma unroll
        for (int j = 0; j < 8; j++)
#pragma unroll
            for (int r = 0; r < 4; r++) s[j][r] = 0.f;
#pragma unroll
        for (int kk = 0; kk < 8; kk++) {
#pragma unroll
            for (int j = 0; j < 8; j++) {
                uint2 bb = *reinterpret_cast<const uint2*>(&Kc[j * 8 + gid][kk * 8 + 2 * tig]);
                unsigned b[2] = { bb.x, bb.y };
                mma8(s[j], qa[kk], b);
            }
        }

        if (has_next) {                    // commit K; prefetch V behind softmax
#pragma unroll
            for (int it = 0; it < 8; it++) {
                int r = ldr + it * 8;
                *reinterpret_cast<uint4*>(&Kn[r][ldc]) = ld[it];
                ld[it] = *reinterpret_cast<const uint4*>(&Vp[(size_t)r * SEQ + sN + ldc]);
            }
        }

        // Online softmax (base 2)
#pragma unroll
        for (int rr = 0; rr < 2; rr++) {
            float mx = -1e30f;
#pragma unroll
            for (int j = 0; j < 8; j++) {
                mx = fmaxf(mx, s[j][rr * 2]);
                mx = fmaxf(mx, s[j][rr * 2 + 1]);
            }
            mx = fmaxf(mx, __shfl_xor_sync(0xffffffffu, mx, 1));
            mx = fmaxf(mx, __shfl_xor_sync(0xffffffffu, mx, 2));
            float mnew = fmaxf(mrow[rr], mx);
            float corr = ex2(mrow[rr] - mnew);
            float rs = 0.f;
#pragma unroll
            for (int j = 0; j < 8; j++) {
                float e0 = ex2(s[j][rr * 2]     - mnew);
                float e1 = ex2(s[j][rr * 2 + 1] - mnew);
                s[j][rr * 2] = e0; s[j][rr * 2 + 1] = e1;
                rs += e0 + e1;
            }
            rs += __shfl_xor_sync(0xffffffffu, rs, 1);
            rs += __shfl_xor_sync(0xffffffffu, rs, 2);
            lrow[rr] = lrow[rr] * corr + rs;
            mrow[rr] = mnew;
#pragma unroll
            for (int j = 0; j < 8; j++) {
                o[j][rr * 2]     *= corr;
                o[j][rr * 2 + 1] *= corr;
            }
        }

        // O += P @ V (P transposed via shuffles; V b-frags via LDS.64)
#pragma unroll
        for (int j = 0; j < 8; j++) {
            unsigned v0 = f2tf(s[j][0]), v1 = f2tf(s[j][1]);
            unsigned v2 = f2tf(s[j][2]), v3 = f2tf(s[j][3]);
            unsigned t00 = __shfl_sync(0xffffffffu, v0, l0);
            unsigned t01 = __shfl_sync(0xffffffffu, v1, l0);
            unsigned t02 = __shfl_sync(0xffffffffu, v2, l0);
            unsigned t03 = __shfl_sync(0xffffffffu, v3, l0);
            unsigned t10 = __shfl_sync(0xffffffffu, v0, l0 + 2);
            unsigned t11 = __shfl_sync(0xffffffffu, v1, l0 + 2);
            unsigned t12 = __shfl_sync(0xffffffffu, v2, l0 + 2);
            unsigned t13 = __shfl_sync(0xffffffffu, v3, l0 + 2);
            unsigned a[4];
            a[0] = odd ? t01 : t00;
            a[1] = odd ? t03 : t02;
            a[2] = odd ? t11 : t10;
            a[3] = odd ? t13 : t12;
#pragma unroll
            for (int jj = 0; jj < 8; jj++) {
                uint2 bb = *reinterpret_cast<const uint2*>(&Vc[jj * 8 + gid][j * 8 + 2 * tig]);
                unsigned b[2] = { bb.x, bb.y };
                mma8(o[jj], a, b);
            }
        }

        if (has_next) {                    // commit V
#pragma unroll
            for (int it = 0; it < 8; it++) {
                int r = ldr + it * 8;
                *reinterpret_cast<uint4*>(&Vn[r][ldc]) = ld[it];
            }
        }
        __syncthreads();                   // single barrier per kv block
    }

    // Epilogue: write g_A tf32-rounded with the gemm k pair-perm
    const int b = bh >> 4, h = bh & 15;
    const float inv0 = 1.f / lrow[0];
    const float inv1 = 1.f / lrow[1];
    const int row0 = q0 + mq + gid;
    const int row1 = row0 + 8;
    const int cofs = (tig < 2) ? 4 * tig : 4 * tig - 7;
#pragma unroll
    for (int jj = 0; jj < 8; jj++) {
        int c0 = h * HD + jj * 8 + cofs;
        outA[(size_t)(b * SEQ + row0) * EMBED + c0    ] =
            __uint_as_float(f2tf(o[jj][0] * inv0));
        outA[(size_t)(b * SEQ + row0) * EMBED + c0 + 2] =
            __uint_as_float(f2tf(o[jj][1] * inv0));
        outA[(size_t)(b * SEQ + row1) * EMBED + c0    ] =
            __uint_as_float(f2tf(o[jj][2] * inv1));
        outA[(size_t)(b * SEQ + row1) * EMBED + c0 + 2] =
            __uint_as_float(f2tf(o[jj][3] * inv1));
    }
}

// ---------------------------------------------------------------------------
// Launch
// ---------------------------------------------------------------------------
extern "C" void kernel_launch(void* const* d_in, const int* in_sizes, int n_in,
                              void* d_out, int out_size)
{
    const float* X  = (const float*)d_in[0];
    const float* Wq = (const float*)d_in[1];
    const float* bq = (const float*)d_in[2];
    const float* Wk = (const float*)d_in[3];
    const float* bk = (const float*)d_in[4];
    const float* Wv = (const float*)d_in[5];
    const float* bv = (const float*)d_in[6];
    const float* Wo = (const float*)d_in[7];
    const float* bo = (const float*)d_in[8];
    float* out = (float*)d_out;

    float *qb, *kb, *vtb, *ab, *xtb, *wtb;
    cudaGetSymbolAddress((void**)&qb,  g_Q);
    cudaGetSymbolAddress((void**)&kb,  g_K);
    cudaGetSymbolAddress((void**)&vtb, g_Vt);
    cudaGetSymbolAddress((void**)&ab,  g_A);
    cudaGetSymbolAddress((void**)&xtb, g_Xt);
    cudaGetSymbolAddress((void**)&wtb, g_Wt);

    cudaFuncSetAttribute(flash_attn, cudaFuncAttributeMaxDynamicSharedMemorySize,
                         FLASH_SMEM_BYTES);
    cudaFuncSetAttribute(gemm_qkv, cudaFuncAttributeMaxDynamicSharedMemorySize,
                         PIPE_SMEM);
    cudaFuncSetAttribute(gemm_out, cudaFuncAttributeMaxDynamicSharedMemorySize,
                         PIPE_SMEM);

    // 1) prep: X tf32 + k-perm; W transpose + tf32 + k-perm
    prep_x<<<(MROWS * EMBED / 4) / 256, 256>>>(X, xtb);
    dim3 wgrid(EMBED / 32, EMBED / 32, 4);
    prep_w<<<wgrid, 256>>>(Wq, Wk, Wv, Wo, wtb);

    // 2) fused QKV projections (Q pre-scaled + tf32; K/Vt tf32)
    dim3 qkvgrid(EMBED / BN, MROWS / BM, 3);     // (8, 32, 3)
    gemm_qkv<<<qkvgrid, 256, PIPE_SMEM>>>(xtb, wtb, bq, bk, bv, qb, kb, vtb);

    // 3) attention
    dim3 fgrid(SEQ / BQ, BATCH * HEADS);         // (32, 32)
    flash_attn<<<fgrid, 128, FLASH_SMEM_BYTES>>>(qb, kb, vtb, ab);

    // 4) output projection
    dim3 ogrid(EMBED / BN, MROWS / BM);          // (8, 32)
    gemm_out<<<ogrid, 256, PIPE_SMEM>>>(ab, wtb, bo, out);
}

// round 17
// speedup vs baseline: 1.5429x; 1.0705x over previous
#include <cuda_runtime.h>
#include <cstdint>
#include <math.h>

#define EMBED 1024
#define HEADS 16
#define HD    64
#define BATCH 2
#define SEQ   2048
#define MROWS (BATCH*SEQ)   /* 4096 */

// ---------------------------------------------------------------------------
// Scratch (device globals: allocation-free per harness rules)
// ---------------------------------------------------------------------------
// Pair-permutation: within every 8-wide block of the contraction-ish dim,
// logical index i is stored at physical position (i<4 ? 2i : 2(i-4)+1).
// Q/K/Vt are stored tf32-rounded (Q additionally pre-scaled by 1/8*log2e),
// so flash staging is a raw cp.async byte copy (no CVT in the mainloop).
__device__ float g_Q [BATCH*HEADS*SEQ*HD];   // [B,H,S,Dh], d-perm, tf32*QSC
__device__ float g_K [BATCH*HEADS*SEQ*HD];   // [B,H,S,Dh], d-perm, tf32
__device__ float g_Vt[BATCH*HEADS*HD*SEQ];   // [B,H,Dh,S], s-perm, tf32
__device__ float g_A [MROWS*EMBED];          // attn out, tf32, k-perm
__device__ float g_Xt[MROWS*EMBED];          // X tf32, k-perm
__device__ float g_Wt[4*EMBED*EMBED];        // W^T [n][k] tf32, k-perm

// ---------------------------------------------------------------------------
// Helpers
// ---------------------------------------------------------------------------
__device__ __forceinline__ unsigned f2tf(float f) {
    unsigned u; asm("cvt.rna.tf32.f32 %0, %1;" : "=r"(u) : "f"(f)); return u;
}
__device__ __forceinline__ uint4 tf4(float4 v) {
    uint4 u; u.x = f2tf(v.x); u.y = f2tf(v.y); u.z = f2tf(v.z); u.w = f2tf(v.w);
    return u;
}
__device__ __forceinline__ float ex2(float x) {
    float y; asm("ex2.approx.f32 %0, %1;" : "=f"(y) : "f"(x)); return y;
}
__device__ __forceinline__ int pp8(int i) {   // pair-perm within 8-block
    return (i < 4) ? 2 * i : 2 * (i - 4) + 1;
}
// D(16x8,f32) += A(16x8,tf32,row) * B(8x8,tf32,col)
__device__ __forceinline__ void mma8(float* c, const unsigned* a, const unsigned* b) {
    asm volatile(
        "mma.sync.aligned.m16n8k8.row.col.f32.tf32.tf32.f32 "
        "{%0,%1,%2,%3},{%4,%5,%6,%7},{%8,%9},{%0,%1,%2,%3};\n"
        : "+f"(c[0]), "+f"(c[1]), "+f"(c[2]), "+f"(c[3])
        : "r"(a[0]), "r"(a[1]), "r"(a[2]), "r"(a[3]), "r"(b[0]), "r"(b[1]));
}

#define CP16(dst, src) \
    asm volatile("cp.async.cg.shared.global [%0], [%1], 16;" :: "r"(dst), "l"(src))
#define CP_COMMIT() asm volatile("cp.async.commit_group;" ::: "memory")
#define CP_WAIT0()  asm volatile("cp.async.wait_group 0;" ::: "memory")

__device__ __forceinline__ uint32_t smem_u32(const void* p) {
    uint32_t a;
    asm("{ .reg .u64 t; cvta.to.shared.u64 t, %1; cvt.u32.u64 %0, t; }" : "=r"(a) : "l"(p));
    return a;
}

#define QSCALE (0.125f * 1.44269504088896340736f)

// ---------------------------------------------------------------------------
// Prep: X -> tf32, k pair-permuted (same row layout).
// ---------------------------------------------------------------------------
__global__ void __launch_bounds__(256)
prep_x(const float* __restrict__ X, float* __restrict__ Xt)
{
    size_t i = (size_t)blockIdx.x * 256 + threadIdx.x;    // float4 index
    float4 v = reinterpret_cast<const float4*>(X)[i];
    uint4  u = tf4(v);
    size_t e = i * 4;
    size_t row = e >> 10;
    int k = (int)(e & 1023);
    float* d = Xt + (row << 10) + (k & ~7) + ((k & 4) ? 1 : 0);
    d[0] = __uint_as_float(u.x);
    d[2] = __uint_as_float(u.y);
    d[4] = __uint_as_float(u.z);
    d[6] = __uint_as_float(u.w);
}

// Prep: W [k][n] -> Wt [n][k], tf32, k pair-permuted. 4 matrices via z.
__global__ void __launch_bounds__(256)
prep_w(const float* __restrict__ W0, const float* __restrict__ W1,
       const float* __restrict__ W2, const float* __restrict__ W3,
       float* __restrict__ Wt)
{
    __shared__ float s[32][33];
    const float* W = (blockIdx.z == 0) ? W0 : (blockIdx.z == 1) ? W1
                    : (blockIdx.z == 2) ? W2 : W3;
    float* o = Wt + (size_t)blockIdx.z * EMBED * EMBED;
    const int kx = blockIdx.y * 32, nx = blockIdx.x * 32;
    const int t = threadIdx.x, r = t >> 3, c = t & 7;

    float4 v = *reinterpret_cast<const float4*>(&W[(size_t)(kx + r) * EMBED + nx + c * 4]);
    int rp = (r & 24) | pp8(r & 7);
    s[c * 4 + 0][rp] = __uint_as_float(f2tf(v.x));
    s[c * 4 + 1][rp] = __uint_as_float(f2tf(v.y));
    s[c * 4 + 2][rp] = __uint_as_float(f2tf(v.z));
    s[c * 4 + 3][rp] = __uint_as_float(f2tf(v.w));
    __syncthreads();
    float4 u;
    u.x = s[r][c * 4 + 0]; u.y = s[r][c * 4 + 1];
    u.z = s[r][c * 4 + 2]; u.w = s[r][c * 4 + 3];
    *reinterpret_cast<float4*>(&o[(size_t)(nx + r) * EMBED + kx + c * 4]) = u;
}

// ---------------------------------------------------------------------------
// Pipelined GEMM: C = A @ W^T + bias, tile 128x128x32, uint2 fragment loads,
// 2-stage cp.async, one barrier per k-tile.
// mode 0: K   -> [B,H,S,Dh] d-perm, tf32-rounded
// mode 1: Q   -> [B,H,S,Dh] d-perm, tf32(v*QSCALE)
// mode 2: Vt  -> [B,H,Dh,S] s-perm, tf32-rounded
// mode 3: out -> row-major [M,N], plain fp32
// ---------------------------------------------------------------------------
#define BM 128
#define BN 128
#define BK 32
#define ASTR 40
#define BSTR 40
#define A_BUF (BM*ASTR*4)
#define B_BUF (BN*BSTR*4)
#define NSTAGE 2
#define PIPE_SMEM (NSTAGE*(A_BUF+B_BUF))   /* 81920 B */
#define NKT (EMBED/BK)

__device__ __forceinline__ void
gemm_pipe_body(const float* __restrict__ A, const float* __restrict__ W,
               const float* __restrict__ bias, float* __restrict__ out, int mode)
{
    extern __shared__ char sm[];
    const uint32_t sb = smem_u32(sm);
    const int t    = threadIdx.x;
    const int w    = t >> 5;
    const int lane = t & 31;
    const int gid  = lane >> 2;
    const int tig  = lane & 3;
    const int wm   = w >> 2;
    const int wn   = w & 3;
    const int m0   = blockIdx.y * BM;
    const int n0   = blockIdx.x * BN;

    uint32_t aoff[NSTAGE], boff[NSTAGE];
#pragma unroll
    for (int s = 0; s < NSTAGE; s++) {
        aoff[s] = sb + s * A_BUF;
        boff[s] = sb + NSTAGE * A_BUF + s * B_BUF;
    }

    auto issue = [&](int slot, int k0) {
#pragma unroll
        for (int it = 0; it < 4; it++) {
            int idx = t + it * 256;
            int r = idx >> 3, c = idx & 7;
            CP16(aoff[slot] + r * (ASTR * 4) + c * 16,
                 A + (size_t)(m0 + r) * EMBED + k0 + c * 4);
        }
#pragma unroll
        for (int it = 0; it < 4; it++) {
            int idx = t + it * 256;
            int r = idx >> 3, c = idx & 7;
            CP16(boff[slot] + r * (BSTR * 4) + c * 16,
                 W + (size_t)(n0 + r) * EMBED + k0 + c * 4);
        }
        CP_COMMIT();
    };

    float acc[4][4][4];
#pragma unroll
    for (int i = 0; i < 4; i++)
#pragma unroll
        for (int j = 0; j < 4; j++)
#pragma unroll
            for (int r = 0; r < 4; r++) acc[i][j][r] = 0.f;

    issue(0, 0);

    for (int kt = 0; kt < NKT; kt++) {
        const int slot = kt & 1;
        CP_WAIT0();
        __syncthreads();
        if (kt + 1 < NKT) issue(slot ^ 1, (kt + 1) * BK);

        const unsigned (*As)[ASTR] = (const unsigned (*)[ASTR])(sm + slot * A_BUF);
        const unsigned (*Bs)[BSTR] =
            (const unsigned (*)[BSTR])(sm + NSTAGE * A_BUF + slot * B_BUF);

#pragma unroll
        for (int kk = 0; kk < BK; kk += 8) {
            unsigned af[4][4], bf[4][2];
#pragma unroll
            for (int i = 0; i < 4; i++) {
                int mb = wm * 64 + i * 16;
                uint2 lo = *reinterpret_cast<const uint2*>(&As[mb + gid    ][kk + 2 * tig]);
                uint2 hi = *reinterpret_cast<const uint2*>(&As[mb + gid + 8][kk + 2 * tig]);
                af[i][0] = lo.x; af[i][1] = hi.x; af[i][2] = lo.y; af[i][3] = hi.y;
            }
#pragma unroll
            for (int j = 0; j < 4; j++) {
                int nb = wn * 32 + j * 8;
                uint2 bb = *reinterpret_cast<const uint2*>(&Bs[nb + gid][kk + 2 * tig]);
                bf[j][0] = bb.x; bf[j][1] = bb.y;
            }
#pragma unroll
            for (int i = 0; i < 4; i++)
#pragma unroll
                for (int j = 0; j < 4; j++)
                    mma8(acc[i][j], af[i], bf[j]);
        }
    }

    // Epilogue (scalar stores; perms + tf32 rounding applied producer-side)
#pragma unroll
    for (int i = 0; i < 4; i++) {
#pragma unroll
        for (int j = 0; j < 4; j++) {
#pragma unroll
            for (int r = 0; r < 4; r++) {
                int m = m0 + wm * 64 + i * 16 + gid + ((r >> 1) << 3);
                int n = n0 + wn * 32 + j * 8 + 2 * tig + (r & 1);
                float v = acc[i][j][r] + bias[n];
                if (mode == 3) {
                    out[(size_t)m * EMBED + n] = v;
                } else {
                    int b = m >> 11, s = m & (SEQ - 1);
                    int h = n >> 6,  d = n & (HD - 1);
                    if (mode == 2) {
                        int sp = (s & ~7) | pp8(s & 7);
                        out[(((size_t)(b * HEADS + h)) * HD + d) * SEQ + sp] =
                            __uint_as_float(f2tf(v));
                    } else {
                        int dp = (d & 56) | pp8(d & 7);
                        float vv = (mode == 1) ? v * QSCALE : v;
                        out[(((size_t)(b * HEADS + h)) * SEQ + s) * HD + dp] =
                            __uint_as_float(f2tf(vv));
                    }
                }
            }
        }
    }
}

__global__ void __launch_bounds__(256, 2)
gemm_qkv(const float* __restrict__ Xt, const float* __restrict__ Wt,
         const float* __restrict__ bq, const float* __restrict__ bk,
         const float* __restrict__ bv,
         float* __restrict__ Qo, float* __restrict__ Ko, float* __restrict__ Vo)
{
    if (blockIdx.z == 0)
        gemm_pipe_body(Xt, Wt,                 bq, Qo, 1);
    else if (blockIdx.z == 1)
        gemm_pipe_body(Xt, Wt + EMBED*EMBED,   bk, Ko, 0);
    else
        gemm_pipe_body(Xt, Wt + 2*EMBED*EMBED, bv, Vo, 2);
}

__global__ void __launch_bounds__(256, 2)
gemm_out(const float* __restrict__ Aa, const float* __restrict__ Wt,
         const float* __restrict__ bias, float* __restrict__ out)
{
    gemm_pipe_body(Aa, Wt + 3*EMBED*EMBED, bias, out, 3);
}

// ---------------------------------------------------------------------------
// Flash attention (R15 cp.async staging — the measured-better variant at
// iso-clock): Q/K/Vt arrive tf32-rounded + permuted; all staging is raw
// cp.async; double-buffered K/V; ONE wait_group + ONE barrier per kv block.
// ---------------------------------------------------------------------------
#define BQ  64
#define BKV 64
#define FL_STRIDE 72
#define TILE_WORDS (BKV * FL_STRIDE)              /* 4608 */
#define FLASH_SMEM_BYTES (4 * TILE_WORDS * 4)     /* 73728 */

__global__ void __launch_bounds__(128, 3)
flash_attn(const float* __restrict__ Q, const float* __restrict__ K,
           const float* __restrict__ Vt, float* __restrict__ outA)
{
    extern __shared__ unsigned sh[];
    unsigned (*Ks0)[FL_STRIDE] = (unsigned (*)[FL_STRIDE])(sh);
    unsigned (*Vs0)[FL_STRIDE] = (unsigned (*)[FL_STRIDE])(sh + TILE_WORDS);
    unsigned (*Ks1)[FL_STRIDE] = (unsigned (*)[FL_STRIDE])(sh + 2 * TILE_WORDS);
    unsigned (*Vs1)[FL_STRIDE] = (unsigned (*)[FL_STRIDE])(sh + 3 * TILE_WORDS);
    const uint32_t sbase = smem_u32(sh);

    const int tid  = threadIdx.x;
    const int w    = tid >> 5;
    const int lane = tid & 31;
    const int gid  = lane >> 2;
    const int tig  = lane & 3;
    const int bh   = blockIdx.y;
    const int q0   = blockIdx.x * BQ;
    const int mq   = w * 16;

    const float* Qp = Q  + (size_t)bh * SEQ * HD;
    const float* Kp = K  + (size_t)bh * SEQ * HD;
    const float* Vp = Vt + (size_t)bh * HD * SEQ;

    const int ldr = tid >> 4;                       // 0..7
    const int ldc = (tid & 15) * 4;                 // word 0..60
    const uint32_t so = (uint32_t)(ldr * FL_STRIDE + ldc) * 4;
    const uint32_t rowstep = 8u * FL_STRIDE * 4u;

    // ---- Q stage via cp.async into Ks0 (64 rows; pre-scaled tf32) ----
#pragma unroll
    for (int it = 0; it < 8; it++)
        CP16(sbase + so + it * rowstep,
             Qp + (size_t)(q0 + ldr + it * 8) * HD + ldc);
    CP_COMMIT(); CP_WAIT0();
    __syncthreads();
    unsigned qa[8][4];
#pragma unroll
    for (int kk = 0; kk < 8; kk++) {
        uint2 lo = *reinterpret_cast<const uint2*>(&Ks0[mq + gid    ][kk * 8 + 2 * tig]);
        uint2 hi = *reinterpret_cast<const uint2*>(&Ks0[mq + gid + 8][kk * 8 + 2 * tig]);
        qa[kk][0] = lo.x; qa[kk][1] = hi.x; qa[kk][2] = lo.y; qa[kk][3] = hi.y;
    }
    __syncthreads();

    // ---- prologue: tile 0 into buffer 0 ----
    const uint32_t KB0 = sbase, VB0 = sbase + TILE_WORDS * 4;
    const uint32_t KB1 = sbase + 2 * TILE_WORDS * 4, VB1 = sbase + 3 * TILE_WORDS * 4;
#pragma unroll
    for (int it = 0; it < 8; it++) {
        int r = ldr + it * 8;
        CP16(KB0 + so + it * rowstep, Kp + (size_t)r * HD + ldc);
        CP16(VB0 + so + it * rowstep, Vp + (size_t)r * SEQ + ldc);
    }
    CP_COMMIT();

    float o[8][4];
#pragma unroll
    for (int j = 0; j < 8; j++)
#pragma unroll
        for (int r = 0; r < 4; r++) o[j][r] = 0.f;
    float mrow[2] = {-1e30f, -1e30f};
    float lrow[2] = {0.f, 0.f};

    const int l0 = (lane & 28) | (tig >> 1);
    const bool odd = (tig & 1);

    for (int kb = 0; kb < SEQ / BKV; kb++) {
        const unsigned (*Kc)[FL_STRIDE] = (kb & 1) ? Ks1 : Ks0;
        const unsigned (*Vc)[FL_STRIDE] = (kb & 1) ? Vs1 : Vs0;
        const uint32_t KnB = (kb & 1) ? KB0 : KB1;
        const uint32_t VnB = (kb & 1) ? VB0 : VB1;
        const bool has_next = (kb + 1) < (SEQ / BKV);
        const int sN = (kb + 1) * BKV;

        CP_WAIT0();                 // current tile resident
        __syncthreads();            // all warps done with the buffer being refilled
        if (has_next) {
#pragma unroll
            for (int it = 0; it < 8; it++) {
                int r = ldr + it * 8;
                CP16(KnB + so + it * rowstep, Kp + (size_t)(sN + r) * HD + ldc);
                CP16(VnB + so + it * rowstep, Vp + (size_t)r * SEQ + sN + ldc);
            }
            CP_COMMIT();
        }

        // S = Q @ K^T  (b-frags via LDS.64)
        float s[8][4];
#pragma unroll
        for (int j = 0; j < 8; j++)
#pragma unroll
            for (int r = 0; r < 4; r++) s[j][r] = 0.f;
#pragma unroll
        for (int kk = 0; kk < 8; kk++) {
#pragma unroll
            for (int j = 0; j < 8; j++) {
                uint2 bb = *reinterpret_cast<const uint2*>(&Kc[j * 8 + gid][kk * 8 + 2 * tig]);
                unsigned b[2] = { bb.x, bb.y };
                mma8(s[j], qa[kk], b);
            }
        }

        // Online softmax (base 2)
#pragma unroll
        for (int rr = 0; rr < 2; rr++) {
            float mx = -1e30f;
#pragma unroll
            for (int j = 0; j < 8; j++) {
                mx = fmaxf(mx, s[j][rr * 2]);
                mx = fmaxf(mx, s[j][rr * 2 + 1]);
            }
            mx = fmaxf(mx, __shfl_xor_sync(0xffffffffu, mx, 1));
            mx = fmaxf(mx, __shfl_xor_sync(0xffffffffu, mx, 2));
            float mnew = fmaxf(mrow[rr], mx);
            float corr = ex2(mrow[rr] - mnew);
            float rs = 0.f;
#pragma unroll
            for (int j = 0; j < 8; j++) {
                float e0 = ex2(s[j][rr * 2]     - mnew);
                float e1 = ex2(s[j][rr * 2 + 1] - mnew);
                s[j][rr * 2] = e0; s[j][rr * 2 + 1] = e1;
                rs += e0 + e1;
            }
            rs += __shfl_xor_sync(0xffffffffu, rs, 1);
            rs += __shfl_xor_sync(0xffffffffu, rs, 2);
            lrow[rr] = lrow[rr] * corr + rs;
            mrow[rr] = mnew;
#pragma unroll
            for (int j = 0; j < 8; j++) {
                o[j][rr * 2]     *= corr;
                o[j][rr * 2 + 1] *= corr;
            }
        }

        // O += P @ V (P transposed via shuffles; V b-frags via LDS.64)
#pragma unroll
        for (int j = 0; j < 8; j++) {
            unsigned v0 = f2tf(s[j][0]), v1 = f2tf(s[j][1]);
            unsigned v2 = f2tf(s[j][2]), v3 = f2tf(s[j][3]);
            unsigned t00 = __shfl_sync(0xffffffffu, v0, l0);
            unsigned t01 = __shfl_sync(0xffffffffu, v1, l0);
            unsigned t02 = __shfl_sync(0xffffffffu, v2, l0);
            unsigned t03 = __shfl_sync(0xffffffffu, v3, l0);
            unsigned t10 = __shfl_sync(0xffffffffu, v0, l0 + 2);
            unsigned t11 = __shfl_sync(0xffffffffu, v1, l0 + 2);
            unsigned t12 = __shfl_sync(0xffffffffu, v2, l0 + 2);
            unsigned t13 = __shfl_sync(0xffffffffu, v3, l0 + 2);
            unsigned a[4];
            a[0] = odd ? t01 : t00;
            a[1] = odd ? t03 : t02;
            a[2] = odd ? t11 : t10;
            a[3] = odd ? t13 : t12;
#pragma unroll
            for (int jj = 0; jj < 8; jj++) {
                uint2 bb = *reinterpret_cast<const uint2*>(&Vc[jj * 8 + gid][j * 8 + 2 * tig]);
                unsigned b[2] = { bb.x, bb.y };
                mma8(o[jj], a, b);
            }
        }
        // no trailing barrier: next iteration's top barrier orders buffer reuse
    }

    // Epilogue: write g_A tf32-rounded with the gemm k pair-perm
    const int b = bh >> 4, h = bh & 15;
    const float inv0 = 1.f / lrow[0];
    const float inv1 = 1.f / lrow[1];
    const int row0 = q0 + mq + gid;
    const int row1 = row0 + 8;
    const int cofs = (tig < 2) ? 4 * tig : 4 * tig - 7;
#pragma unroll
    for (int jj = 0; jj < 8; jj++) {
        int c0 = h * HD + jj * 8 + cofs;
        outA[(size_t)(b * SEQ + row0) * EMBED + c0    ] =
            __uint_as_float(f2tf(o[jj][0] * inv0));
        outA[(size_t)(b * SEQ + row0) * EMBED + c0 + 2] =
            __uint_as_float(f2tf(o[jj][1] * inv0));
        outA[(size_t)(b * SEQ + row1) * EMBED + c0    ] =
            __uint_as_float(f2tf(o[jj][2] * inv1));
        outA[(size_t)(b * SEQ + row1) * EMBED + c0 + 2] =
            __uint_as_float(f2tf(o[jj][3] * inv1));
    }
}

// ---------------------------------------------------------------------------
// Launch
// ---------------------------------------------------------------------------
extern "C" void kernel_launch(void* const* d_in, const int* in_sizes, int n_in,
                              void* d_out, int out_size)
{
    const float* X  = (const float*)d_in[0];
    const float* Wq = (const float*)d_in[1];
    const float* bq = (const float*)d_in[2];
    const float* Wk = (const float*)d_in[3];
    const float* bk = (const float*)d_in[4];
    const float* Wv = (const float*)d_in[5];
    const float* bv = (const float*)d_in[6];
    const float* Wo = (const float*)d_in[7];
    const float* bo = (const float*)d_in[8];
    float* out = (float*)d_out;

    float *qb, *kb, *vtb, *ab, *xtb, *wtb;
    cudaGetSymbolAddress((void**)&qb,  g_Q);
    cudaGetSymbolAddress((void**)&kb,  g_K);
    cudaGetSymbolAddress((void**)&vtb, g_Vt);
    cudaGetSymbolAddress((void**)&ab,  g_A);
    cudaGetSymbolAddress((void**)&xtb, g_Xt);
    cudaGetSymbolAddress((void**)&wtb, g_Wt);

    cudaFuncSetAttribute(flash_attn, cudaFuncAttributeMaxDynamicSharedMemorySize,
                         FLASH_SMEM_BYTES);
    cudaFuncSetAttribute(gemm_qkv, cudaFuncAttributeMaxDynamicSharedMemorySize,
                         PIPE_SMEM);
    cudaFuncSetAttribute(gemm_out, cudaFuncAttributeMaxDynamicSharedMemorySize,
                         PIPE_SMEM);

    // 1) prep: X tf32 + k-perm; W transpose + tf32 + k-perm
    prep_x<<<(MROWS * EMBED / 4) / 256, 256>>>(X, xtb);
    dim3 wgrid(EMBED / 32, EMBED / 32, 4);
    prep_w<<<wgrid, 256>>>(Wq, Wk, Wv, Wo, wtb);

    // 2) fused QKV projections (Q pre-scaled + tf32; K/Vt tf32)
    dim3 qkvgrid(EMBED / BN, MROWS / BM, 3);     // (8, 32, 3)
    gemm_qkv<<<qkvgrid, 256, PIPE_SMEM>>>(xtb, wtb, bq, bk, bv, qb, kb, vtb);

    // 3) attention
    dim3 fgrid(SEQ / BQ, BATCH * HEADS);         // (32, 32)
    flash_attn<<<fgrid, 128, FLASH_SMEM_BYTES>>>(qb, kb, vtb, ab);

    // 4) output projection
    dim3 ogrid(EMBED / BN, MROWS / BM);          // (8, 32)
    gemm_out<<<ogrid, 256, PIPE_SMEM>>>(ab, wtb, bo, out);
}